// round 3
// baseline (speedup 1.0000x reference)
#include <cuda_runtime.h>
#include <math_constants.h>
#include <cstdint>

#define N_TOKENS 262144
#define D_MODEL  1024
#define ALPHA    0.5f
#define WINDOW   64          // 0.5^64 ~ 5e-20: tail truncation far below 1e-3 rel-err

// Scratch for per-token scores (1 MB). Device global: no allocation in kernel_launch.
__device__ float g_scores[N_TOKENS];

// -------------------------------------------------------------------------
// Kernel 1: scores[row] = dot(x[row, :], W) + b   (memory-bound, ~1 GB read)
// Warp-per-row, float4 loads, W staged in smem, shfl reduction.
// -------------------------------------------------------------------------
__global__ __launch_bounds__(256)
void score_kernel(const float* __restrict__ x,
                  const float* __restrict__ W,
                  const float* __restrict__ b,
                  float* __restrict__ out,
                  int n_rows)
{
    __shared__ float4 w4[D_MODEL / 4];     // 4 KB

    const int tid = threadIdx.x;

    // Stage W into shared (broadcast-read later, conflict-free)
    #pragma unroll
    for (int i = tid; i < D_MODEL / 4; i += 256)
        w4[i] = reinterpret_cast<const float4*>(W)[i];

    // Initialize output to -inf (d_out is poisoned to 0xAA before timing)
    if (blockIdx.x == 0 && tid == 0)
        *out = -CUDART_INF_F;

    __syncthreads();

    const float bias = __ldg(b);
    const int warp   = tid >> 5;
    const int lane   = tid & 31;
    const int gwarp  = blockIdx.x * 8 + warp;       // 8 warps/block
    const int nwarps = gridDim.x * 8;

    for (int row = gwarp; row < n_rows; row += nwarps) {
        const float4* xr =
            reinterpret_cast<const float4*>(x + (size_t)row * D_MODEL);
        float acc = 0.f;
        #pragma unroll
        for (int i = 0; i < 8; i++) {               // 8 independent LDG.128 (MLP)
            float4 xv = xr[lane + i * 32];
            float4 wv = w4[lane + i * 32];
            acc = fmaf(xv.x, wv.x, acc);
            acc = fmaf(xv.y, wv.y, acc);
            acc = fmaf(xv.z, wv.z, acc);
            acc = fmaf(xv.w, wv.w, acc);
        }
        #pragma unroll
        for (int o = 16; o; o >>= 1)
            acc += __shfl_xor_sync(0xffffffffu, acc, o);
        if (lane == 0)
            g_scores[row] = acc + bias;
    }
}

// -------------------------------------------------------------------------
// Kernel 2: windowed EMA (exact to ~1e-19) + global max via float atomicMax.
// ema_j = sum_{k=0..WINDOW-1} 0.5^{k+1} * s_{j-k}, s_{<0} treated as 0
// (matches EMA_0 = 0 initial state of the reference recurrence).
// -------------------------------------------------------------------------
__device__ __forceinline__ void atomic_max_float(float* addr, float val)
{
    if (val >= 0.f)
        atomicMax(reinterpret_cast<int*>(addr), __float_as_int(val));
    else
        atomicMin(reinterpret_cast<unsigned int*>(addr), __float_as_uint(val));
}

__global__ __launch_bounds__(256)
void ema_max_kernel(float* __restrict__ out, int n)
{
    __shared__ float s[256 + WINDOW];
    __shared__ float wmax[8];

    const int tid  = threadIdx.x;
    const int base = blockIdx.x * 256;

    // Load chunk + left halo; clamp negative indices to 0 (pre-sequence state).
    #pragma unroll
    for (int i = tid; i < 256 + WINDOW; i += 256) {
        int idx = base - WINDOW + i;
        s[i] = (idx >= 0 && idx < n) ? g_scores[idx] : 0.f;
    }
    __syncthreads();

    // Windowed EMA for position j = base + tid (smem index tid + WINDOW).
    float acc = 0.f;
    float w   = ALPHA;                       // fully unrolled -> coeffs fold to imm
    #pragma unroll
    for (int k = 0; k < WINDOW; k++) {
        acc = fmaf(w, s[tid + WINDOW - k], acc);
        w *= (1.0f - ALPHA);
    }
    if (base + tid >= n) acc = -CUDART_INF_F;

    // Block max reduction
    #pragma unroll
    for (int o = 16; o; o >>= 1)
        acc = fmaxf(acc, __shfl_xor_sync(0xffffffffu, acc, o));
    if ((tid & 31) == 0) wmax[tid >> 5] = acc;
    __syncthreads();
    if (tid < 8) {
        float m = wmax[tid];
        #pragma unroll
        for (int o = 4; o; o >>= 1)
            m = fmaxf(m, __shfl_xor_sync(0xffu, m, o));
        if (tid == 0)
            atomic_max_float(out, m);
    }
}

// -------------------------------------------------------------------------
extern "C" void kernel_launch(void* const* d_in, const int* in_sizes, int n_in,
                              void* d_out, int out_size)
{
    const float* x = (const float*)d_in[0];
    const float* W = (const float*)d_in[1];
    const float* b = (const float*)d_in[2];
    float* out     = (float*)d_out;

    const int n = in_sizes[0] / D_MODEL;    // 262144

    // 8 warps/block, 4 rows/warp per grid-stride pass
    const int grid1 = (n + 8 * 4 - 1) / (8 * 4);      // 8192 blocks
    score_kernel<<<grid1, 256>>>(x, W, b, out, n);

    const int grid2 = (n + 255) / 256;                 // 1024 blocks
    ema_max_kernel<<<grid2, 256>>>(out, n);
}